// round 7
// baseline (speedup 1.0000x reference)
#include <cuda_runtime.h>

#define B_N 16
#define K_N 20
#define H_N 256
#define W_N 256
#define HW_N 65536
#define RAD 4
#define STRIP_H 64
#define PADH 72      // STRIP_H + 2*RAD (divisible by 9)
#define NSTRIP 4
#define NPART (B_N*NSTRIP)   // 64 partials per class
#define KG 2                 // k's per stats block
#define CH 16                // HW chunks in stats
#define KM 2                 // classes per main block

__device__ float g_stats4[B_N * K_N * CH * 4];
__device__ float g_num[K_N * NPART];
__device__ float g_den[K_N * NPART];

// ---------------------------------------------------------------------------
// Kernel 1: per-(b,k) partial sums over an HW chunk:
//   sum(labels), sum(labels*x_c) c=0..2.  KG k's per block to amortize x loads.
// ---------------------------------------------------------------------------
__global__ __launch_bounds__(256) void stats_kernel(const float* __restrict__ labels,
                                                    const float* __restrict__ inputs) {
    const int kt = blockIdx.x, b = blockIdx.y, ch = blockIdx.z, t = threadIdx.x;
    const int chunk = HW_N / CH;       // 4096 floats
    const int nf4 = chunk / 4;         // 1024 float4

    const float4* X0 = (const float4*)(inputs + (size_t)(b * 3 + 0) * HW_N + ch * chunk);
    const float4* X1 = (const float4*)(inputs + (size_t)(b * 3 + 1) * HW_N + ch * chunk);
    const float4* X2 = (const float4*)(inputs + (size_t)(b * 3 + 2) * HW_N + ch * chunk);
    const float4* L[KG];
    #pragma unroll
    for (int kk = 0; kk < KG; kk++)
        L[kk] = (const float4*)(labels + (size_t)(b * K_N + kt * KG + kk) * HW_N + ch * chunk);

    float acc[KG][4];
    #pragma unroll
    for (int kk = 0; kk < KG; kk++)
        #pragma unroll
        for (int j = 0; j < 4; j++) acc[kk][j] = 0.f;

    #pragma unroll 4
    for (int i = t; i < nf4; i += 256) {
        const float4 x0 = X0[i], x1 = X1[i], x2 = X2[i];
        #pragma unroll
        for (int kk = 0; kk < KG; kk++) {
            const float4 l = L[kk][i];
            acc[kk][0] += (l.x + l.y) + (l.z + l.w);
            acc[kk][1] = fmaf(l.x, x0.x, fmaf(l.y, x0.y, fmaf(l.z, x0.z, fmaf(l.w, x0.w, acc[kk][1]))));
            acc[kk][2] = fmaf(l.x, x1.x, fmaf(l.y, x1.y, fmaf(l.z, x1.z, fmaf(l.w, x1.w, acc[kk][2]))));
            acc[kk][3] = fmaf(l.x, x2.x, fmaf(l.y, x2.y, fmaf(l.z, x2.z, fmaf(l.w, x2.w, acc[kk][3]))));
        }
    }

    #pragma unroll
    for (int kk = 0; kk < KG; kk++)
        #pragma unroll
        for (int j = 0; j < 4; j++)
            #pragma unroll
            for (int o = 16; o; o >>= 1)
                acc[kk][j] += __shfl_down_sync(0xffffffffu, acc[kk][j], o);

    __shared__ float red[8][KG * 4];
    const int wid = t >> 5, lane = t & 31;
    if (lane == 0) {
        #pragma unroll
        for (int kk = 0; kk < KG; kk++)
            #pragma unroll
            for (int j = 0; j < 4; j++) red[wid][kk * 4 + j] = acc[kk][j];
    }
    __syncthreads();
    if (t < KG * 4) {
        float v = 0.f;
        #pragma unroll
        for (int w = 0; w < 8; w++) v += red[w][t];
        const int k = kt * KG + (t >> 2);
        g_stats4[((b * K_N + k) * CH + ch) * 4 + (t & 3)] = v;
    }
}

// ---------------------------------------------------------------------------
// Kernel 2: adjoint-fused main pass, barrier-free, 2 cols/thread, 2 classes
// per block (input loads amortized across the class pair).
//   num_k = sum (l*w) * blur(l),  den_k = sum w * blur(l)
// h-blur: 5 overlapping float2 loads per class per row (L1-cached).
// v-blur: 9-deep register rings, static indices. Center raw label re-loaded
// at output rows (L1 hit).
// ---------------------------------------------------------------------------
__global__ __launch_bounds__(128) void main_kernel(const float* __restrict__ labels,
                                                   const float* __restrict__ inputs) {
    const int t = threadIdx.x;
    const int s = blockIdx.x;    // strip 0..3
    const int kp = blockIdx.y;   // class pair
    const int b = blockIdx.z;

    // g(d) = exp(-d^2 / (2*5^2)) -> literal immediates (FFMA-imm, rt=1)
    constexpr float G[9] = {0.72614903f, 0.83527021f, 0.92311635f, 0.98019867f, 1.0f,
                            0.98019867f, 0.92311635f, 0.83527021f, 0.72614903f};

    const int k0 = kp * KM, k1 = k0 + 1;

    __shared__ float sstat[8];
    if (t < 8) {
        const int k = k0 + (t >> 2);
        float v = 0.f;
        #pragma unroll
        for (int ch = 0; ch < CH; ch++)
            v += g_stats4[((b * K_N + k) * CH + ch) * 4 + (t & 3)];
        sstat[t] = v;
    }
    __syncthreads();
    // class_mean_c = sumX_c / (sumL + 1e-5*HW)
    const float invA = 1.0f / (sstat[0] + 0.65536f);
    const float cmA0 = sstat[1] * invA, cmA1 = sstat[2] * invA, cmA2 = sstat[3] * invA;
    const float invB = 1.0f / (sstat[4] + 0.65536f);
    const float cmB0 = sstat[5] * invB, cmB1 = sstat[6] * invB, cmB2 = sstat[7] * invB;

    const float* labA = labels + (size_t)(b * K_N + k0) * HW_N;
    const float* labB = labels + (size_t)(b * K_N + k1) * HW_N;
    const float* xp0 = inputs + (size_t)(b * 3) * HW_N;
    const float* xp1 = xp0 + HW_N;
    const float* xp2 = xp1 + HW_N;

    const int row0 = s * STRIP_H - RAD;   // global row of padded row 0
    const int oc0 = 2 * t;                // this thread's two output columns

    // validity of the 5 overlapping float2 loads (per-thread const)
    bool vld[5];
    #pragma unroll
    for (int i = 0; i < 5; i++) {
        const int col = oc0 - 4 + 2 * i;
        vld[i] = ((unsigned)col < (unsigned)W_N);
    }

    float rA0[9], rA1[9], rB0[9], rB1[9];   // rings: h-blurred labels (class A/B)
    float nA = 0.f, dA = 0.f, nB = 0.f, dB = 0.f;

    for (int prb = 0; prb < PADH; prb += 9) {
        #pragma unroll
        for (int u = 0; u < 9; u++) {
            const int pr = prb + u;
            const int gr = row0 + pr;
            const bool rowOK = ((unsigned)gr < (unsigned)H_N);
            const int roff = gr * W_N + oc0;

            // --- class A: 10-value window + h-blur ---
            {
                const float* rp = labA + roff;
                float v[10];
                #pragma unroll
                for (int i = 0; i < 5; i++) {
                    float2 a = make_float2(0.f, 0.f);
                    if (rowOK && vld[i]) a = __ldg((const float2*)(rp - 4 + 2 * i));
                    v[2 * i] = a.x; v[2 * i + 1] = a.y;
                }
                float h0 = v[0] * G[0], h1 = v[1] * G[0];
                #pragma unroll
                for (int j = 1; j < 9; j++) {
                    h0 = fmaf(v[j],     G[j], h0);
                    h1 = fmaf(v[j + 1], G[j], h1);
                }
                rA0[u] = h0; rA1[u] = h1;
            }
            // --- class B: 10-value window + h-blur ---
            {
                const float* rp = labB + roff;
                float v[10];
                #pragma unroll
                for (int i = 0; i < 5; i++) {
                    float2 a = make_float2(0.f, 0.f);
                    if (rowOK && vld[i]) a = __ldg((const float2*)(rp - 4 + 2 * i));
                    v[2 * i] = a.x; v[2 * i + 1] = a.y;
                }
                float h0 = v[0] * G[0], h1 = v[1] * G[0];
                #pragma unroll
                for (int j = 1; j < 9; j++) {
                    h0 = fmaf(v[j],     G[j], h0);
                    h1 = fmaf(v[j + 1], G[j], h1);
                }
                rB0[u] = h0; rB1[u] = h1;
            }

            // --- vertical 9-tap completes output row gor = s*64 + pr - 8 ---
            if (pr >= 8) {
                float BA0 = 0.f, BA1 = 0.f, BB0 = 0.f, BB1 = 0.f;
                #pragma unroll
                for (int j = 0; j < 9; j++) {
                    const int slot = (u + 1 + j) % 9;   // (pr-8+j)%9, static
                    BA0 = fmaf(rA0[slot], G[j], BA0);
                    BA1 = fmaf(rA1[slot], G[j], BA1);
                    BB0 = fmaf(rB0[slot], G[j], BB0);
                    BB1 = fmaf(rB1[slot], G[j], BB1);
                }

                const int gor = s * STRIP_H + pr - 8;
                const int idx = gor * W_N + oc0;
                const float2 x0 = __ldg((const float2*)(xp0 + idx));
                const float2 x1 = __ldg((const float2*)(xp1 + idx));
                const float2 x2 = __ldg((const float2*)(xp2 + idx));
                const float2 lA = __ldg((const float2*)(labA + idx));  // L1 hit
                const float2 lB = __ldg((const float2*)(labB + idx));  // L1 hit

                // class A weights
                {
                    const float a0 = x0.x - cmA0, a1 = x1.x - cmA1, a2 = x2.x - cmA2;
                    const float dd = fmaf(a0, a0, fmaf(a1, a1, a2 * a2));
                    const float w = __expf(-dd * dd);
                    nA = fmaf(lA.x * w, BA0, nA);
                    dA = fmaf(w, BA0, dA);
                }
                {
                    const float a0 = x0.y - cmA0, a1 = x1.y - cmA1, a2 = x2.y - cmA2;
                    const float dd = fmaf(a0, a0, fmaf(a1, a1, a2 * a2));
                    const float w = __expf(-dd * dd);
                    nA = fmaf(lA.y * w, BA1, nA);
                    dA = fmaf(w, BA1, dA);
                }
                // class B weights
                {
                    const float a0 = x0.x - cmB0, a1 = x1.x - cmB1, a2 = x2.x - cmB2;
                    const float dd = fmaf(a0, a0, fmaf(a1, a1, a2 * a2));
                    const float w = __expf(-dd * dd);
                    nB = fmaf(lB.x * w, BB0, nB);
                    dB = fmaf(w, BB0, dB);
                }
                {
                    const float a0 = x0.y - cmB0, a1 = x1.y - cmB1, a2 = x2.y - cmB2;
                    const float dd = fmaf(a0, a0, fmaf(a1, a1, a2 * a2));
                    const float w = __expf(-dd * dd);
                    nB = fmaf(lB.y * w, BB1, nB);
                    dB = fmaf(w, BB1, dB);
                }
            }
        }
    }

    // --- deterministic block reduction ---
    #pragma unroll
    for (int o = 16; o; o >>= 1) {
        nA += __shfl_down_sync(0xffffffffu, nA, o);
        dA += __shfl_down_sync(0xffffffffu, dA, o);
        nB += __shfl_down_sync(0xffffffffu, nB, o);
        dB += __shfl_down_sync(0xffffffffu, dB, o);
    }
    __shared__ float rn[2][4], rd[2][4];
    if ((t & 31) == 0) {
        rn[0][t >> 5] = nA; rd[0][t >> 5] = dA;
        rn[1][t >> 5] = nB; rd[1][t >> 5] = dB;
    }
    __syncthreads();
    if (t < 2) {
        const float n = (rn[t][0] + rn[t][1]) + (rn[t][2] + rn[t][3]);
        const float d = (rd[t][0] + rd[t][1]) + (rd[t][2] + rd[t][3]);
        const int idx = ((k0 + t) * B_N + b) * NSTRIP + s;
        g_num[idx] = n;
        g_den[idx] = d;
    }
}

// ---------------------------------------------------------------------------
// Kernel 3: final deterministic reduction -> scalar loss
// ---------------------------------------------------------------------------
__global__ void finish_kernel(float* __restrict__ out) {
    __shared__ float sv[K_N];
    const int t = threadIdx.x;
    if (t < K_N) {
        float n = 0.f, d = 0.f;
        for (int i = 0; i < NPART; i++) {
            n += g_num[t * NPART + i];
            d += g_den[t * NPART + i];
        }
        sv[t] = fabsf(n / (d + 1e-6f));
    }
    __syncthreads();
    if (t == 0) {
        float loss = 0.f;
        for (int i = 0; i < K_N; i++) loss += sv[i];
        out[0] = (float)K_N - loss;
    }
}

// ---------------------------------------------------------------------------
extern "C" void kernel_launch(void* const* d_in, const int* in_sizes, int n_in,
                              void* d_out, int out_size) {
    (void)n_in; (void)out_size;
    const float* labels;
    const float* inputs;
    if (in_sizes[0] == B_N * K_N * HW_N) {
        labels = (const float*)d_in[0];
        inputs = (const float*)d_in[1];
    } else {
        labels = (const float*)d_in[1];
        inputs = (const float*)d_in[0];
    }
    float* out = (float*)d_out;

    stats_kernel<<<dim3(K_N / KG, B_N, CH), 256>>>(labels, inputs);
    main_kernel<<<dim3(NSTRIP, K_N / KM, B_N), 128>>>(labels, inputs);
    finish_kernel<<<1, 32>>>(out);
}

// round 8
// speedup vs baseline: 1.2502x; 1.2502x over previous
#include <cuda_runtime.h>
#include <cuda_pipeline_primitives.h>

#define B_N 16
#define K_N 20
#define H_N 256
#define W_N 256
#define HW_N 65536
#define RAD 4
#define STRIP_H 64
#define PADH 72      // STRIP_H + 2*RAD (divisible by 9)
#define NSTRIP 4
#define NPART (B_N*NSTRIP)   // 64 partials per class
#define KG 2                 // k's per stats block
#define CH 16                // HW chunks in stats
#define GR 9                 // rows per async group
#define NG (PADH/GR)         // 8 groups
#define SROWS (2*GR)         // 18-row smem ring (2 groups)
#define SW 264               // padded row width in smem

__device__ float g_stats4[B_N * K_N * CH * 4];
__device__ float g_num[K_N * NPART];
__device__ float g_den[K_N * NPART];

// ---------------------------------------------------------------------------
// Kernel 1: per-(b,k) partial sums over an HW chunk:
//   sum(labels), sum(labels*x_c) c=0..2.  KG k's per block to amortize x loads.
// ---------------------------------------------------------------------------
__global__ __launch_bounds__(256) void stats_kernel(const float* __restrict__ labels,
                                                    const float* __restrict__ inputs) {
    const int kt = blockIdx.x, b = blockIdx.y, ch = blockIdx.z, t = threadIdx.x;
    const int chunk = HW_N / CH;       // 4096 floats
    const int nf4 = chunk / 4;         // 1024 float4

    const float4* X0 = (const float4*)(inputs + (size_t)(b * 3 + 0) * HW_N + ch * chunk);
    const float4* X1 = (const float4*)(inputs + (size_t)(b * 3 + 1) * HW_N + ch * chunk);
    const float4* X2 = (const float4*)(inputs + (size_t)(b * 3 + 2) * HW_N + ch * chunk);
    const float4* L[KG];
    #pragma unroll
    for (int kk = 0; kk < KG; kk++)
        L[kk] = (const float4*)(labels + (size_t)(b * K_N + kt * KG + kk) * HW_N + ch * chunk);

    float acc[KG][4];
    #pragma unroll
    for (int kk = 0; kk < KG; kk++)
        #pragma unroll
        for (int j = 0; j < 4; j++) acc[kk][j] = 0.f;

    #pragma unroll 4
    for (int i = t; i < nf4; i += 256) {
        const float4 x0 = X0[i], x1 = X1[i], x2 = X2[i];
        #pragma unroll
        for (int kk = 0; kk < KG; kk++) {
            const float4 l = L[kk][i];
            acc[kk][0] += (l.x + l.y) + (l.z + l.w);
            acc[kk][1] = fmaf(l.x, x0.x, fmaf(l.y, x0.y, fmaf(l.z, x0.z, fmaf(l.w, x0.w, acc[kk][1]))));
            acc[kk][2] = fmaf(l.x, x1.x, fmaf(l.y, x1.y, fmaf(l.z, x1.z, fmaf(l.w, x1.w, acc[kk][2]))));
            acc[kk][3] = fmaf(l.x, x2.x, fmaf(l.y, x2.y, fmaf(l.z, x2.z, fmaf(l.w, x2.w, acc[kk][3]))));
        }
    }

    #pragma unroll
    for (int kk = 0; kk < KG; kk++)
        #pragma unroll
        for (int j = 0; j < 4; j++)
            #pragma unroll
            for (int o = 16; o; o >>= 1)
                acc[kk][j] += __shfl_down_sync(0xffffffffu, acc[kk][j], o);

    __shared__ float red[8][KG * 4];
    const int wid = t >> 5, lane = t & 31;
    if (lane == 0) {
        #pragma unroll
        for (int kk = 0; kk < KG; kk++)
            #pragma unroll
            for (int j = 0; j < 4; j++) red[wid][kk * 4 + j] = acc[kk][j];
    }
    __syncthreads();
    if (t < KG * 4) {
        float v = 0.f;
        #pragma unroll
        for (int w = 0; w < 8; w++) v += red[w][t];
        const int k = kt * KG + (t >> 2);
        g_stats4[((b * K_N + k) * CH + ch) * 4 + (t & 3)] = v;
    }
}

// ---------------------------------------------------------------------------
// Kernel 2: adjoint-fused main pass with cp.async label staging.
//   num_k = sum (l*w) * blur(l),  den_k = sum w * blur(l)
// Labels staged 9 rows/group, 2 groups in flight (cp.async) -> DRAM latency
// hidden. h-blur reads 10-value windows from smem (LDS). v-blur: 9-deep
// register rings, static indices. 2 barriers per group (16/block).
// Block = 128 threads = one (b,k,strip); thread owns 2 output columns.
// ---------------------------------------------------------------------------
__global__ __launch_bounds__(128) void main_kernel(const float* __restrict__ labels,
                                                   const float* __restrict__ inputs) {
    const int t = threadIdx.x;
    const int s = blockIdx.x;   // strip 0..3
    const int k = blockIdx.y;
    const int b = blockIdx.z;

    // g(d) = exp(-d^2 / (2*5^2)) -> literal immediates (FFMA-imm, rt=1)
    constexpr float G[9] = {0.72614903f, 0.83527021f, 0.92311635f, 0.98019867f, 1.0f,
                            0.98019867f, 0.92311635f, 0.83527021f, 0.72614903f};

    __shared__ float sTile[SROWS][SW];   // 18 x 264 floats = 19008 B
    __shared__ float sstat[4];

    if (t < 4) {
        float v = 0.f;
        #pragma unroll
        for (int ch = 0; ch < CH; ch++)
            v += g_stats4[((b * K_N + k) * CH + ch) * 4 + t];
        sstat[t] = v;
    }
    // zero the permanent horizontal pad columns (0..3 and 260..263) of all rows
    if (t < SROWS * 8) {
        const int r = t >> 3, c = t & 7;
        sTile[r][(c < 4) ? c : (SW - 8 + c)] = 0.f;
    }

    const float* lab = labels + (size_t)(b * K_N + k) * HW_N;
    const float* xp0 = inputs + (size_t)(b * 3) * HW_N;
    const float* xp1 = xp0 + HW_N;
    const float* xp2 = xp1 + HW_N;

    const int row0 = s * STRIP_H - RAD;   // global row of padded row 0
    const int oc0 = 2 * t;                // this thread's two output columns

    // --- stage one 9-row group: 9 rows x 64 float4 chunks (valid cols) ---
    auto stage = [&](int g) {
        #pragma unroll
        for (int task = t; task < GR * 64; task += 128) {
            const int r  = task >> 6;       // 0..8
            const int c4 = task & 63;       // 0..63
            const int pr = g * GR + r;
            const int gr = row0 + pr;
            float* dst = &sTile[pr % SROWS][4 + c4 * 4];
            if ((unsigned)gr < (unsigned)H_N) {
                __pipeline_memcpy_async(dst, lab + gr * W_N + c4 * 4, 16);
            } else {
                *(float4*)dst = make_float4(0.f, 0.f, 0.f, 0.f);
            }
        }
    };

    stage(0); __pipeline_commit();
    stage(1); __pipeline_commit();

    float rb0[9], rb1[9];   // ring: h-blurred labels
    float ra0[9], ra1[9];   // ring: raw center labels
    float numAcc = 0.f, denAcc = 0.f;

    for (int g = 0; g < NG; g++) {
        __pipeline_wait_prior(1);
        __syncthreads();          // group g resident (also publishes sstat/pads on g=0)

        const float inv = 1.0f / (sstat[0] + 0.65536f);
        const float cm0 = sstat[1] * inv, cm1 = sstat[2] * inv, cm2 = sstat[3] * inv;

        #pragma unroll
        for (int u = 0; u < 9; u++) {
            const int pr = g * GR + u;
            const float* srow = &sTile[pr % SROWS][oc0];  // pad col oc0 = global col oc0-4

            // --- 10-value horizontal window: 5 float2 LDS ---
            float v[10];
            #pragma unroll
            for (int i = 0; i < 5; i++) {
                const float2 a = *(const float2*)(srow + 2 * i);
                v[2 * i] = a.x; v[2 * i + 1] = a.y;
            }

            // --- horizontal 9-tap ---
            float h0 = v[0] * G[0], h1 = v[1] * G[0];
            #pragma unroll
            for (int j = 1; j < 9; j++) {
                h0 = fmaf(v[j],     G[j], h0);
                h1 = fmaf(v[j + 1], G[j], h1);
            }
            rb0[u] = h0; rb1[u] = h1;          // slot pr%9 == u
            ra0[u] = v[4]; ra1[u] = v[5];      // raw labels at own cols

            // --- vertical 9-tap completes output row gor = s*64 + pr - 8 ---
            if (pr >= 8) {
                float B0 = 0.f, B1 = 0.f;
                #pragma unroll
                for (int j = 0; j < 9; j++) {
                    const int slot = (u + 1 + j) % 9;   // (pr-8+j)%9, static
                    B0 = fmaf(rb0[slot], G[j], B0);
                    B1 = fmaf(rb1[slot], G[j], B1);
                }
                const int cs = (u + 5) % 9;             // slot of center row (pr-4)
                const float l0 = ra0[cs], l1 = ra1[cs];

                const int gor = s * STRIP_H + pr - 8;
                const int idx = gor * W_N + oc0;
                const float2 x0 = __ldg((const float2*)(xp0 + idx));
                const float2 x1 = __ldg((const float2*)(xp1 + idx));
                const float2 x2 = __ldg((const float2*)(xp2 + idx));

                const float a0 = x0.x - cm0, a1 = x1.x - cm1, a2 = x2.x - cm2;
                const float d0 = fmaf(a0, a0, fmaf(a1, a1, a2 * a2));
                const float c0 = x0.y - cm0, c1 = x1.y - cm1, c2 = x2.y - cm2;
                const float d1 = fmaf(c0, c0, fmaf(c1, c1, c2 * c2));
                const float w0 = __expf(-d0 * d0);
                const float w1 = __expf(-d1 * d1);

                numAcc = fmaf(l0 * w0, B0, numAcc);
                numAcc = fmaf(l1 * w1, B1, numAcc);
                denAcc = fmaf(w0, B0, denAcc);
                denAcc = fmaf(w1, B1, denAcc);
            }
        }

        __syncthreads();          // all threads done reading group g
        if (g + 2 < NG) { stage(g + 2); }
        __pipeline_commit();      // keep group accounting uniform
    }

    // --- deterministic block reduction ---
    #pragma unroll
    for (int o = 16; o; o >>= 1) {
        numAcc += __shfl_down_sync(0xffffffffu, numAcc, o);
        denAcc += __shfl_down_sync(0xffffffffu, denAcc, o);
    }
    __shared__ float rn[4], rd[4];
    if ((t & 31) == 0) { rn[t >> 5] = numAcc; rd[t >> 5] = denAcc; }
    __syncthreads();
    if (t == 0) {
        const float n = (rn[0] + rn[1]) + (rn[2] + rn[3]);
        const float d = (rd[0] + rd[1]) + (rd[2] + rd[3]);
        const int idx = (k * B_N + b) * NSTRIP + s;
        g_num[idx] = n;
        g_den[idx] = d;
    }
}

// ---------------------------------------------------------------------------
// Kernel 3: final deterministic reduction -> scalar loss
// ---------------------------------------------------------------------------
__global__ void finish_kernel(float* __restrict__ out) {
    __shared__ float sv[K_N];
    const int t = threadIdx.x;
    if (t < K_N) {
        float n = 0.f, d = 0.f;
        for (int i = 0; i < NPART; i++) {
            n += g_num[t * NPART + i];
            d += g_den[t * NPART + i];
        }
        sv[t] = fabsf(n / (d + 1e-6f));
    }
    __syncthreads();
    if (t == 0) {
        float loss = 0.f;
        for (int i = 0; i < K_N; i++) loss += sv[i];
        out[0] = (float)K_N - loss;
    }
}

// ---------------------------------------------------------------------------
extern "C" void kernel_launch(void* const* d_in, const int* in_sizes, int n_in,
                              void* d_out, int out_size) {
    (void)n_in; (void)out_size;
    const float* labels;
    const float* inputs;
    if (in_sizes[0] == B_N * K_N * HW_N) {
        labels = (const float*)d_in[0];
        inputs = (const float*)d_in[1];
    } else {
        labels = (const float*)d_in[1];
        inputs = (const float*)d_in[0];
    }
    float* out = (float*)d_out;

    stats_kernel<<<dim3(K_N / KG, B_N, CH), 256>>>(labels, inputs);
    main_kernel<<<dim3(NSTRIP, K_N, B_N), 128>>>(labels, inputs);
    finish_kernel<<<1, 32>>>(out);
}